// round 2
// baseline (speedup 1.0000x reference)
#include <cuda_runtime.h>
#include <cstdint>

#define NPTS 262144
#define CHN 96
#define KOFF 27
#define TM 64
#define KK 32
#define NTHREADS 256

// Intermediate activations between the two conv layers (100 MB, static — no allocs).
__device__ float g_x1[(size_t)NPTS * CHN];

// One gather-GEMM-scatter sparse-conv layer:
//   out[p][c] = PReLU( sum_k sum_j (mask[k][p] ? fin[idx[k][p]][j] : 0) * W[k][j][c]
//               + bias[c] + (resid ? resid[p][c] : 0), alpha )
__global__ void __launch_bounds__(NTHREADS, 4)
sconv_kernel(const float* __restrict__ fin,
             const float* __restrict__ resid,      // nullptr for layer 1
             const int* __restrict__ nidx,         // [K, N]
             const int* __restrict__ nmask,        // [K, N] (bool stored as int32)
             const float* __restrict__ W,          // [K, CH, CH]
             const float* __restrict__ bias,       // [CH]
             const float* __restrict__ alpha,      // [1]
             float* __restrict__ out)              // [N, CH]
{
    __shared__ float As[KK][TM + 1];     // gathered features, transposed [kk][t]
    __shared__ float Bs[KK][CHN];        // weight tile [kk][c]
    __shared__ int   sIdx[KOFF][TM];
    __shared__ unsigned char sMsk[KOFF][TM];

    const int tid  = threadIdx.x;
    const int base = blockIdx.x * TM;

    // Preload neighbor indices + masks for this block's 64 points, all 27 offsets.
    for (int o = tid; o < KOFF * TM; o += NTHREADS) {
        const int k = o / TM, t = o % TM;
        sIdx[k][t] = nidx[(size_t)k * NPTS + base + t];
        sMsk[k][t] = (unsigned char)(nmask[(size_t)k * NPTS + base + t] != 0);
    }

    const int tx = tid & 15;        // channel group -> c0 = tx*6 (3 f32x2 pairs)
    const int ty = tid >> 4;        // point group   -> t0 = ty*4
    const int c0 = tx * 6;
    const int t0 = ty * 4;

    // Packed f32x2 accumulators: 4 points x 3 channel-pairs.
    unsigned long long acc[4][3];
    #pragma unroll
    for (int t = 0; t < 4; ++t)
        #pragma unroll
        for (int p = 0; p < 3; ++p) acc[t][p] = 0ull;

    // Gather-fill mapping: 4 threads per point, 8 consecutive floats each.
    const int ft = tid >> 2;        // point 0..63
    const int fq = tid & 3;         // quarter of the 32-wide j-slice

    __syncthreads();

    const int NTILES = (KOFF * CHN) / KK;   // 81; each tile lies in one k (96 = 3*32)
    for (int tile = 0; tile < NTILES; ++tile) {
        const int k  = tile / 3;
        const int j0 = (tile % 3) * KK;

        // ---- fill As: masked gather of fin rows, transposed into [kk][t] ----
        {
            const int  row = sIdx[k][ft];
            const bool m   = sMsk[k][ft] != 0;
            float4 v0 = make_float4(0.f, 0.f, 0.f, 0.f), v1 = v0;
            if (m) {
                const float* src = fin + (size_t)row * CHN + j0 + fq * 8;
                v0 = *reinterpret_cast<const float4*>(src);
                v1 = *reinterpret_cast<const float4*>(src + 4);
            }
            const int kb = fq * 8;
            As[kb + 0][ft] = v0.x; As[kb + 1][ft] = v0.y;
            As[kb + 2][ft] = v0.z; As[kb + 3][ft] = v0.w;
            As[kb + 4][ft] = v1.x; As[kb + 5][ft] = v1.y;
            As[kb + 6][ft] = v1.z; As[kb + 7][ft] = v1.w;
        }

        // ---- fill Bs: W[k][j0..j0+31][0..95] (contiguous 3072 floats) ----
        {
            const float* wsrc = W + (size_t)k * CHN * CHN + (size_t)j0 * CHN;
            #pragma unroll
            for (int pass = 0; pass < 3; ++pass) {
                const int o = (tid + pass * NTHREADS) * 4;   // 0..3068, step 4
                const float4 v = *reinterpret_cast<const float4*>(wsrc + o);
                *reinterpret_cast<float4*>(&Bs[o / CHN][o % CHN]) = v;
            }
        }
        __syncthreads();

        // ---- compute: 32 reduction steps, 12 packed FMAs each ----
        #pragma unroll
        for (int kk = 0; kk < KK; ++kk) {
            unsigned long long gp[4];
            #pragma unroll
            for (int t = 0; t < 4; ++t) {
                const float g = As[kk][t0 + t];
                asm("mov.b64 %0, {%1, %1};" : "=l"(gp[t]) : "f"(g));
            }
            #pragma unroll
            for (int p = 0; p < 3; ++p) {
                const unsigned long long wp =
                    *reinterpret_cast<const unsigned long long*>(&Bs[kk][c0 + 2 * p]);
                #pragma unroll
                for (int t = 0; t < 4; ++t)
                    asm("fma.rn.f32x2 %0, %1, %2, %0;"
                        : "+l"(acc[t][p]) : "l"(gp[t]), "l"(wp));
            }
        }
        __syncthreads();
    }

    // ---- epilogue: bias, optional residual, PReLU, store ----
    const float a0 = alpha[0];
    #pragma unroll
    for (int t = 0; t < 4; ++t) {
        const int pt = base + t0 + t;
        #pragma unroll
        for (int p = 0; p < 3; ++p) {
            float x0, x1;
            asm("mov.b64 {%0, %1}, %2;" : "=f"(x0), "=f"(x1) : "l"(acc[t][p]));
            const int c = c0 + 2 * p;
            float v0 = x0 + bias[c];
            float v1 = x1 + bias[c + 1];
            if (resid != nullptr) {
                v0 += resid[(size_t)pt * CHN + c];
                v1 += resid[(size_t)pt * CHN + c + 1];
            }
            v0 = (v0 > 0.f) ? v0 : a0 * v0;
            v1 = (v1 > 0.f) ? v1 : a0 * v1;
            out[(size_t)pt * CHN + c]     = v0;
            out[(size_t)pt * CHN + c + 1] = v1;
        }
    }
}

extern "C" void kernel_launch(void* const* d_in, const int* in_sizes, int n_in,
                              void* d_out, int out_size)
{
    const float* feats = (const float*)d_in[0];
    const int*   idx   = (const int*)d_in[1];
    const int*   mask  = (const int*)d_in[2];
    const float* W1    = (const float*)d_in[3];
    const float* b1    = (const float*)d_in[4];
    const float* a1    = (const float*)d_in[5];
    const float* W2    = (const float*)d_in[6];
    const float* b2    = (const float*)d_in[7];
    const float* a2    = (const float*)d_in[8];
    float*       out   = (float*)d_out;

    float* x1 = nullptr;
    cudaGetSymbolAddress((void**)&x1, g_x1);

    dim3 grid(NPTS / TM), block(NTHREADS);
    sconv_kernel<<<grid, block>>>(feats, nullptr, idx, mask, W1, b1, a1, x1);
    sconv_kernel<<<grid, block>>>(x1,    feats,   idx, mask, W2, b2, a2, out);
}